// round 10
// baseline (speedup 1.0000x reference)
#include <cuda_runtime.h>
#include <math.h>
#include <stdint.h>

#define NQ    20
#define NL    4
#define BATCH 16
#define DIM   (1 << NQ)

#define CB      8                      // batches per chunk
#define NCHUNK  (BATCH / CB)

__device__ float  g_bufA[CB * DIM];
__device__ float  g_bufB[CB * DIM];
__device__ float2 g_rf[NL * NQ];   // .x = ratio (|r|<=1), .y = form (0 or 1)
__device__ float  g_absC;          // |product of per-gate scales|

// ---------------------------------------------------------------------------
// Fast-Givens precompute.
//   form0 (|c|>=|s|): M = c*[[1,-t],[t,1]], t=s/c
//   form1 (|s|> |c|): M = s*[[u,-1],[1,u]], u=c/s
// ---------------------------------------------------------------------------
__global__ void sincos_kernel(const float* __restrict__ theta) {
    __shared__ float sc[NL * NQ];
    int i = threadIdx.x;
    if (i < NL * NQ) {
        float t = 0.5f * theta[i];
        float c = cosf(t), s = sinf(t);
        bool form = fabsf(s) > fabsf(c);
        g_rf[i] = make_float2(form ? (c / s) : (s / c), form ? 1.0f : 0.0f);
        sc[i] = form ? s : c;
    }
    __syncthreads();
    if (i == 0) {
        float p = 1.0f;
        for (int k = 0; k < NL * NQ; k++) p *= sc[k];
        g_absC = fabsf(p);
    }
}

// ---------------------------------------------------------------------------
// Packed f32x2 helpers (sm_103a FFMA2 via PTX)
// ---------------------------------------------------------------------------
union F2U { float2 f; unsigned long long u; };

__device__ __forceinline__ float2 ffma2(float2 a, float2 b, float2 c) {
    F2U ua, ub, uc, ud;
    ua.f = a; ub.f = b; uc.f = c;
    asm("fma.rn.f32x2 %0, %1, %2, %3;" : "=l"(ud.u) : "l"(ua.u), "l"(ub.u), "l"(uc.u));
    return ud.f;
}
__device__ __forceinline__ float2 neg2(float2 v) {
    F2U x; x.f = v; x.u ^= 0x8000000080000000ULL; return x.f;
}

// Packed butterfly stage over 16 float2 (mask on float2 index).
__device__ __forceinline__ void pstage16(float2* v, int m, float2 rf) {
    float2 r2  = make_float2(rf.x, rf.x);
    float2 nr2 = make_float2(-rf.x, -rf.x);
    if (rf.y == 0.0f) {
#pragma unroll
        for (int i = 0; i < 16; i++)
            if ((i & m) == 0) {
                float2 a = v[i], b = v[i | m];
                v[i]     = ffma2(nr2, b, a);
                v[i | m] = ffma2(r2,  a, b);
            }
    } else {
#pragma unroll
        for (int i = 0; i < 16; i++)
            if ((i & m) == 0) {
                float2 a = v[i], b = v[i | m];
                v[i]     = ffma2(r2, a, neg2(b));
                v[i | m] = ffma2(r2, b, a);
            }
    }
}

// Packed cross-lane stage: lane bit kbit. bit=0 -> role 'a'.
__device__ __forceinline__ void pshuf16(float2* v, int kbit, float2 rf, int lane) {
    int bit = (lane >> kbit) & 1;
    if (rf.y == 0.0f) {
        float rs = bit ? rf.x : -rf.x;
        float2 rs2 = make_float2(rs, rs);
#pragma unroll
        for (int i = 0; i < 16; i++) {
            float2 o;
            o.x = __shfl_xor_sync(0xffffffffu, v[i].x, 1 << kbit);
            o.y = __shfl_xor_sync(0xffffffffu, v[i].y, 1 << kbit);
            v[i] = ffma2(rs2, o, v[i]);
        }
    } else {
        float2 r2 = make_float2(rf.x, rf.x);
        unsigned long long sg = bit ? 0ULL : 0x8000000080000000ULL;
#pragma unroll
        for (int i = 0; i < 16; i++) {
            F2U o;
            o.f.x = __shfl_xor_sync(0xffffffffu, v[i].x, 1 << kbit);
            o.f.y = __shfl_xor_sync(0xffffffffu, v[i].y, 1 << kbit);
            o.u ^= sg;
            v[i] = ffma2(r2, v[i], o.f);
        }
    }
}

// Within-pair stage (idx bit 0: x='a', y='b')
__device__ __forceinline__ float2 pair_stage(float2 v, float2 rf) {
    float2 o;
    if (rf.y == 0.0f) {
        o.x = fmaf(-rf.x, v.y, v.x);
        o.y = fmaf( rf.x, v.x, v.y);
    } else {
        o.x = fmaf(rf.x, v.x, -v.y);
        o.y = fmaf(rf.x, v.y,  v.x);
    }
    return o;
}

// ---------------------------------------------------------------------------
// Scalar fast-Givens butterflies (hh / ph kernels)
// ---------------------------------------------------------------------------
template <int N>
__device__ __forceinline__ void stage_fg(float* e, int m, float2 rf) {
    float r = rf.x;
    if (rf.y == 0.0f) {
#pragma unroll
        for (int j = 0; j < N; j++)
            if ((j & m) == 0) {
                float a = e[j], b = e[j | m];
                e[j]     = fmaf(-r, b, a);
                e[j | m] = fmaf( r, a, b);
            }
    } else {
#pragma unroll
        for (int j = 0; j < N; j++)
            if ((j & m) == 0) {
                float a = e[j], b = e[j | m];
                e[j]     = fmaf(r, a, -b);
                e[j | m] = fmaf(r, b,  a);
            }
    }
}

// Conjugated H stage (P^-1 H P): couples u-pairs differing in bits {hb, hb-1};
// role(u) = parity(u >> hb).
template <int HB>
__device__ __forceinline__ void conj_stage(float e[64], float2 rf) {
    const int mask = 3 << (HB - 1);
    float r = rf.x;
    bool f1 = (rf.y != 0.0f);
    if (!f1) {
#pragma unroll
        for (int u = 0; u < 64; u++)
            if ((u & (1 << HB)) == 0) {
                int v = u ^ mask;
                int ra = __popc(u >> HB) & 1;
                int ia = ra ? v : u;
                int ib = ra ? u : v;
                float a = e[ia], b = e[ib];
                e[ia] = fmaf(-r, b, a);
                e[ib] = fmaf( r, a, b);
            }
    } else {
#pragma unroll
        for (int u = 0; u < 64; u++)
            if ((u & (1 << HB)) == 0) {
                int v = u ^ mask;
                int ra = __popc(u >> HB) & 1;
                int ia = ra ? v : u;
                int ib = ra ? u : v;
                float a = e[ia], b = e[ib];
                e[ia] = fmaf(r, a, -b);
                e[ib] = fmaf(r, b,  a);
            }
    }
}

// Conjugated R5(layer1) stage inside hh: couples g bits {14,13} = (reg bit 0,
// lane bit 0). Partner of e[u] is shfl_xor(e[u^1], 1). Role 'a' = parity(u)==0.
__device__ __forceinline__ void conj_r5_stage(float e[64], float2 rf) {
    float r = rf.x;
    bool f1 = (rf.y != 0.0f);
#pragma unroll
    for (int u = 0; u < 64; u += 2) {
        float o0 = __shfl_xor_sync(0xffffffffu, e[u + 1], 1);
        float o1 = __shfl_xor_sync(0xffffffffu, e[u],     1);
        bool aFirst = ((__popc(u) & 1) == 0);
        if (!f1) {
            if (aFirst) {
                e[u]     = fmaf(-r, o0, e[u]);
                e[u + 1] = fmaf( r, o1, e[u + 1]);
            } else {
                e[u]     = fmaf( r, o0, e[u]);
                e[u + 1] = fmaf(-r, o1, e[u + 1]);
            }
        } else {
            if (aFirst) {
                e[u]     = fmaf(r, e[u],     -o0);
                e[u + 1] = fmaf(r, e[u + 1],  o1);
            } else {
                e[u]     = fmaf(r, e[u],      o0);
                e[u + 1] = fmaf(r, e[u + 1], -o1);
            }
        }
    }
}

// gray decode (p such that p ^ (p>>1) = g)
__device__ __host__ __forceinline__ int gdec(int g) {
    int p = g;
    p ^= p >> 1; p ^= p >> 2; p ^= p >> 4; p ^= p >> 8; p ^= p >> 16;
    return p;
}
__device__ __forceinline__ int gd6(int u) {
    int p = u; p ^= p >> 1; p ^= p >> 2; p ^= p >> 4; return p & 63;
}

// ---------------------------------------------------------------------------
// HH kernel: (R5_l1) * H1 * P * (H0 x R5_l0). Orbit = g bits 19:14; pos bit 13
// on lane bit 0. Grid-stride x2 (grid 256 -> one wave at 2 CTAs/SM).
// ---------------------------------------------------------------------------
__global__ void __launch_bounds__(256, 2) hh_kernel(const float* __restrict__ in,
                                                    float* __restrict__ out) {
    const int tid = threadIdx.x;
    const int t0  = tid & 1;
    const int w   = tid >> 5;
    const int tl  = (tid >> 1) & 15;
    const float2* rf0 = g_rf;
    const float2* rf1 = g_rf + NQ;

    for (int it = 0; it < 2; it++) {
        const int blk = blockIdx.x + it * 256;
        const int sub = blk & 63;
        const int pos = (t0 << 13) | (sub << 7) | (w << 4) | tl;
        const size_t bbase = (size_t)(blk >> 6) << 20;

        float e[64];
        const float* pin = in + bbase + pos;
#pragma unroll
        for (int u = 0; u < 64; u++) e[u] = pin[u << 14];

        stage_fg<64>(e, 32, rf0[0]);
        stage_fg<64>(e, 16, rf0[1]);
        stage_fg<64>(e,  8, rf0[2]);
        stage_fg<64>(e,  4, rf0[3]);
        stage_fg<64>(e,  2, rf0[4]);
        stage_fg<64>(e,  1, rf0[5]);

        conj_stage<5>(e, rf1[0]);
        conj_stage<4>(e, rf1[1]);
        conj_stage<3>(e, rf1[2]);
        conj_stage<2>(e, rf1[3]);
        conj_stage<1>(e, rf1[4]);
        conj_r5_stage(e, rf1[5]);

        const int A = gdec(pos);
        float* pa = out + bbase + A;
        float* pb = out + bbase + (A ^ 0x3FFF);
#pragma unroll
        for (int u = 0; u < 64; u++) {
            int hi = gd6(u) << 14;
            if (__popc(u) & 1) pb[hi] = e[u];
            else               pa[hi] = e[u];
        }
    }
}

// ---------------------------------------------------------------------------
// PH kernel: (H_l x R5_l) * P, 64-element orbit. Grid-stride x2.
// ---------------------------------------------------------------------------
__global__ void __launch_bounds__(256, 2) ph_kernel(const float* __restrict__ in,
                                                    float* __restrict__ out,
                                                    int layer) {
    const float2* rf = g_rf + layer * NQ;
    for (int it = 0; it < 2; it++) {
        const int blk = blockIdx.x + it * 256;
        const int pos = (blk & 63) * 256 + threadIdx.x;
        const size_t bbase = (size_t)(blk >> 6) << 20;
        const int G = pos ^ (pos >> 1);

        float e[64];
        const float* pin = in + bbase;
#pragma unroll
        for (int k = 0; k < 64; k++)
            e[k] = pin[((k << 14) ^ (k << 13)) ^ G];

        stage_fg<64>(e, 32, rf[0]);
        stage_fg<64>(e, 16, rf[1]);
        stage_fg<64>(e,  8, rf[2]);
        stage_fg<64>(e,  4, rf[3]);
        stage_fg<64>(e,  2, rf[4]);
        stage_fg<64>(e,  1, rf[5]);

        float* pout = out + bbase + pos;
#pragma unroll
        for (int k = 0; k < 64; k++) pout[k << 14] = e[k];
    }
}

// ---------------------------------------------------------------------------
// LOW14 kernel (f32x2): qubits 6..19, 16384-float tiles, float2 data path.
// Thread (w 4b, t 5b); float2 unit a64 = jj*512 + w*32 + t.
// idx = a64*2 + p0:  bit0=p0(q19), 5:1=t(q18..14), 9:6=w(q13..10), 13:10=jj(q9..6)
// Phase1: pair(q19) + shuffles(q18..14) + packed jj(q9..6).
// Transpose (float2, conflict-free). Phase2: packed n(q13..10).
// Grid 256, 2 tiles/CTA. FINAL: gray scatter as swapped float2 pairs.
// ---------------------------------------------------------------------------
template <bool FINAL>
__global__ void __launch_bounds__(512, 2) low14_kernel(const float* in,
                                                       float* out,
                                                       int layer) {
    extern __shared__ float2 sm2[];        // 8192 float2 = 64 KB
    const int t = threadIdx.x & 31;
    const int w = threadIdx.x >> 5;        // 0..15
    const float2* rf = g_rf + layer * NQ;

    for (int it = 0; it < 2; it++) {
        const int blk  = blockIdx.x + it * 256;
        const int tile = blk & 63;
        const size_t bbase = (size_t)(blk >> 6) << 20;
        const size_t tb2   = (bbase + ((size_t)tile << 14)) >> 1;   // float2 units

        float2 v[16];
        const float2* p2 = ((const float2*)in) + tb2;
#pragma unroll
        for (int jj = 0; jj < 16; jj++) v[jj] = p2[jj * 512 + w * 32 + t];

        // q19 (within pair)
#pragma unroll
        for (int jj = 0; jj < 16; jj++) v[jj] = pair_stage(v[jj], rf[19]);
        // shuffles: lane bit k <-> qubit 18-k
        pshuf16(v, 0, rf[18], t);
        pshuf16(v, 1, rf[17], t);
        pshuf16(v, 2, rf[16], t);
        pshuf16(v, 3, rf[15], t);
        pshuf16(v, 4, rf[14], t);
        // packed jj stages: mask m <-> qubit 9 - log2(m)
        pstage16(v, 1, rf[9]);
        pstage16(v, 2, rf[8]);
        pstage16(v, 4, rf[7]);
        pstage16(v, 8, rf[6]);

        __syncthreads();                   // smem reuse guard across tiles
#pragma unroll
        for (int jj = 0; jj < 16; jj++) sm2[jj * 512 + w * 32 + t] = v[jj];
        __syncthreads();
#pragma unroll
        for (int n = 0; n < 16; n++) v[n] = sm2[(w << 9) | (n << 5) | t];

        // packed n stages: mask m <-> qubit 13 - log2(m)
        pstage16(v, 1, rf[13]);
        pstage16(v, 2, rf[12]);
        pstage16(v, 4, rf[11]);
        pstage16(v, 8, rf[10]);

        if (FINAL) {
            const float absC = g_absC;
            const int pbase = gdec((tile << 14) | (w << 10) | (t << 1));
            float* o = out + bbase;
#pragma unroll
            for (int n = 0; n < 16; n++) {
                int A = pbase ^ gdec(n << 6);      // folds to const per n
                float ax = fabsf(v[n].x) * absC;
                float ay = fabsf(v[n].y) * absC;
                float2 sv = (A & 1) ? make_float2(ay, ax) : make_float2(ax, ay);
                *((float2*)(o + (A & ~1))) = sv;
            }
        } else {
            float2* q2 = ((float2*)out) + tb2;
#pragma unroll
            for (int n = 0; n < 16; n++) q2[(w << 9) | (n << 5) | t] = v[n];
        }
    }
}

// ---------------------------------------------------------------------------
extern "C" void kernel_launch(void* const* d_in, const int* in_sizes, int n_in,
                              void* d_out, int out_size) {
    const float* x     = (const float*)d_in[0];
    const float* theta = (const float*)d_in[1];
    float*       out   = (float*)d_out;

    float *bA = nullptr, *bB = nullptr;
    cudaGetSymbolAddress((void**)&bA, g_bufA);
    cudaGetSymbolAddress((void**)&bB, g_bufB);

    const int SM14 = 8192 * sizeof(float2);   // 64 KB
    cudaFuncSetAttribute(low14_kernel<false>, cudaFuncAttributeMaxDynamicSharedMemorySize, SM14);
    cudaFuncSetAttribute(low14_kernel<true>,  cudaFuncAttributeMaxDynamicSharedMemorySize, SM14);

    sincos_kernel<<<1, 128>>>(theta);

    const int G = 256;   // one full wave at 2 CTAs/SM; 2 units per CTA

    for (int c = 0; c < NCHUNK; c++) {
        const float* xc = x   + ((size_t)c * CB << 20);
        float*       oc = out + ((size_t)c * CB << 20);

        low14_kernel<false><<<G, 512, SM14>>>(xc, bA, 0);  // L0 (q6..19)
        hh_kernel<<<G, 256>>>(bA, bB);                     // R5l1*H1*P*(H0,R5l0)
        low14_kernel<false><<<G, 512, SM14>>>(bB, bB, 1);  // L1 (in-place)
        ph_kernel<<<G, 256>>>(bB, bA, 2);                  // (H2,R5l2) * P
        low14_kernel<false><<<G, 512, SM14>>>(bA, bA, 2);  // L2 (in-place)
        ph_kernel<<<G, 256>>>(bA, bB, 3);                  // (H3,R5l3) * P
        low14_kernel<true><<<G, 512, SM14>>>(bB, oc, 3);   // P * L3, abs*|C|
    }
}